// round 15
// baseline (speedup 1.0000x reference)
#include <cuda_runtime.h>
#include <cuda_fp16.h>
#include <math.h>

// Problem shapes (fixed by the dataset)
constexpr int B   = 512;
constexpr int N   = 8192;
constexpr int H   = 200;
constexpr int W   = 200;
constexpr int ENV = H * W;            // 40000 cells
constexpr int THREADS = 512;
constexpr int PPT = N / THREADS;      // 16 points per thread

// Scratch for cross-block reduction (no device-side allocation allowed)
__device__ float        g_partials[B];
__device__ unsigned int g_count = 0;  // self-resetting via atomicInc wrap

__global__ __launch_bounds__(THREADS, 2)
void collision_fused_kernel(const float* __restrict__ opState,
                            const float* __restrict__ envs,
                            float* __restrict__ out)
{
    extern __shared__ __align__(16) unsigned char smem_raw[];
    __half* env_s = reinterpret_cast<__half*>(smem_raw);                   // 80000 B
    double* redd  = reinterpret_cast<double*>(smem_raw + ENV * sizeof(__half)); // 16 doubles
    float*  redf  = reinterpret_cast<float*>(redd);                        // aliased (phases are sync-separated)
    volatile int* last_flag = reinterpret_cast<volatile int*>(redd + 16);

    const int b    = blockIdx.x;
    const int tid  = threadIdx.x;
    const int warp = tid >> 5;
    const int lane = tid & 31;

    // ---- 1) Prefetch this thread's 16 points into registers (overlaps slab stream) ----
    const float2* pts = reinterpret_cast<const float2*>(opState + (size_t)b * N * 2);
    float2 p[PPT];
    #pragma unroll
    for (int j = 0; j < PPT; j++)
        p[j] = pts[tid + j * THREADS];

    // ---- 2) Stream slab HBM(fp32) -> smem(fp16), coalesced float4 reads ----
    {
        const float4* src = reinterpret_cast<const float4*>(envs + (size_t)b * ENV);
        __half2*      dst = reinterpret_cast<__half2*>(env_s);
        for (int i = tid; i < ENV / 4; i += THREADS) {
            float4 v = src[i];
            dst[2 * i]     = __floats2half2_rn(v.x, v.y);
            dst[2 * i + 1] = __floats2half2_rn(v.z, v.w);
        }
    }
    __syncthreads();

    // ---- 3) Bilinear gather + penalty for 16 points (all operands in regs/smem) ----
    float acc = 0.0f;
    #pragma unroll
    for (int j = 0; j < PPT; j++) {
        float pxr = p[j].x, pyr = p[j].y;
        bool oor = (pxr < -9.9f) || (pxr > 9.9f) || (pyr < -9.9f) || (pyr > 9.9f);

        float px = fminf(fmaxf(pxr, -9.9f), 9.9f);
        float py = fminf(fmaxf(pyr, -9.9f), 9.9f);

        // Reference op order: idx = floor(((pos - 0.05) + 10) / 0.1)
        float tx = ((px - 0.05f) + 10.0f) / 0.1f;
        float ty = ((py - 0.05f) + 10.0f) / 0.1f;
        int ix = (int)floorf(tx);
        int iy = (int)floorf(ty);
        ix = min(max(ix, 0), H - 2);   // mathematically already in range; memory safety only
        iy = min(max(iy, 0), W - 2);

        float cx = ((float)ix + 0.5f) * 0.1f - 10.0f;
        float cy = ((float)iy + 0.5f) * 0.1f - 10.0f;
        float dx = (px - cx) / 0.1f;
        float dy = (py - cy) / 0.1f;

        const __half* r0 = env_s + ix * W + iy;
        float v00 = __half2float(r0[0]);
        float v01 = __half2float(r0[1]);
        float v10 = __half2float(r0[W]);
        float v11 = __half2float(r0[W + 1]);

        float vx0 = (1.0f - dx) * v00 + dx * v10;
        float vx1 = (1.0f - dx) * v01 + dx * v11;
        float v   = (1.0f - dy) * vx0 + dy * vx1;

        float d    = oor ? -1.0f : v;
        float viod = fmaxf(10.0f * (0.3f - d), 0.0f);
        acc = fmaf(viod, viod, acc);
    }

    // ---- 4) Block reduction (fp32) ----
    #pragma unroll
    for (int o = 16; o > 0; o >>= 1)
        acc += __shfl_xor_sync(0xffffffffu, acc, o);
    if (lane == 0) redf[warp] = acc;
    __syncthreads();

    if (warp == 0) {
        float s = (lane < THREADS / 32) ? redf[lane] : 0.0f;
        #pragma unroll
        for (int o = 16; o > 0; o >>= 1)
            s += __shfl_xor_sync(0xffffffffu, s, o);
        if (lane == 0) g_partials[b] = s;
    }
    __syncthreads();   // redf reads done before last_flag/redd reuse

    // ---- 5) Last-block-finishes finalization (fence + atomicInc wrap, deterministic) ----
    if (tid == 0) {
        __threadfence();                                   // publish g_partials[b]
        unsigned int old = atomicInc(&g_count, B - 1);     // wraps to 0 on the B-th arrival
        *last_flag = (old == (unsigned int)(B - 1)) ? 1 : 0;
    }
    __syncthreads();

    if (*last_flag) {
        __threadfence();                   // acquire side: see all blocks' partials
        double v = (double)__ldcg(&g_partials[tid]);       // 512 threads, one partial each

        #pragma unroll
        for (int o = 16; o > 0; o >>= 1)
            v += __shfl_xor_sync(0xffffffffu, v, o);
        if (lane == 0) redd[warp] = v;
        __syncthreads();

        if (warp == 0) {
            double s = (lane < THREADS / 32) ? redd[lane] : 0.0;
            #pragma unroll
            for (int o = 8; o > 0; o >>= 1)
                s += __shfl_xor_sync(0xffffffffu, s, o);
            if (lane == 0)
                out[0] = (float)(s / ((double)B * (double)N));
        }
    }
}

extern "C" void kernel_launch(void* const* d_in, const int* in_sizes, int n_in,
                              void* d_out, int out_size)
{
    const float* opState = (const float*)d_in[0];   // (B, N, 2) float32
    const float* envs    = (const float*)d_in[1];   // (B, 1, H, W) float32
    float*       out     = (float*)d_out;           // scalar float32

    // 80000 B slab + 128 B reduce scratch + 16 B flag
    constexpr int SMEM_BYTES = ENV * sizeof(__half) + 16 * sizeof(double) + 16;

    cudaFuncSetAttribute(collision_fused_kernel,
                         cudaFuncAttributeMaxDynamicSharedMemorySize, SMEM_BYTES);

    collision_fused_kernel<<<B, THREADS, SMEM_BYTES>>>(opState, envs, out);
}

// round 16
// speedup vs baseline: 1.0036x; 1.0036x over previous
#include <cuda_runtime.h>
#include <cuda_fp16.h>
#include <math.h>

// Problem shapes (fixed by the dataset)
constexpr int B   = 512;
constexpr int N   = 8192;
constexpr int H   = 200;
constexpr int W   = 200;
constexpr int ENV = H * W;            // 40000 cells
constexpr int THREADS = 512;
constexpr int PPT = N / THREADS;      // 16 points per thread

// Scratch for cross-block reduction (no device-side allocation allowed)
__device__ float        g_partials[B];
__device__ unsigned int g_count = 0;  // self-resetting via atomicInc wrap

__global__ __launch_bounds__(THREADS, 2)
void collision_fused_kernel(const float* __restrict__ opState,
                            const float* __restrict__ envs,
                            float* __restrict__ out)
{
    extern __shared__ __align__(16) unsigned char smem_raw[];
    __half* env_s = reinterpret_cast<__half*>(smem_raw);                   // 80000 B
    double* redd  = reinterpret_cast<double*>(smem_raw + ENV * sizeof(__half)); // 16 doubles
    float*  redf  = reinterpret_cast<float*>(redd);                        // aliased (phases are sync-separated)
    volatile int* last_flag = reinterpret_cast<volatile int*>(redd + 16);

    const int b    = blockIdx.x;
    const int tid  = threadIdx.x;
    const int warp = tid >> 5;
    const int lane = tid & 31;

    // ---- 1) Prefetch this thread's 16 points into registers (overlaps slab stream) ----
    const float2* pts = reinterpret_cast<const float2*>(opState + (size_t)b * N * 2);
    float2 p[PPT];
    #pragma unroll
    for (int j = 0; j < PPT; j++)
        p[j] = pts[tid + j * THREADS];

    // ---- 2) Stream slab HBM(fp32) -> smem(fp16), coalesced float4 reads ----
    {
        const float4* src = reinterpret_cast<const float4*>(envs + (size_t)b * ENV);
        __half2*      dst = reinterpret_cast<__half2*>(env_s);
        for (int i = tid; i < ENV / 4; i += THREADS) {
            float4 v = src[i];
            dst[2 * i]     = __floats2half2_rn(v.x, v.y);
            dst[2 * i + 1] = __floats2half2_rn(v.z, v.w);
        }
    }
    __syncthreads();

    // ---- 3) Bilinear gather + penalty for 16 points (all operands in regs/smem) ----
    float acc = 0.0f;
    #pragma unroll
    for (int j = 0; j < PPT; j++) {
        float pxr = p[j].x, pyr = p[j].y;
        bool oor = (pxr < -9.9f) || (pxr > 9.9f) || (pyr < -9.9f) || (pyr > 9.9f);

        float px = fminf(fmaxf(pxr, -9.9f), 9.9f);
        float py = fminf(fmaxf(pyr, -9.9f), 9.9f);

        // Reference op order: idx = floor(((pos - 0.05) + 10) / 0.1)
        float tx = ((px - 0.05f) + 10.0f) / 0.1f;
        float ty = ((py - 0.05f) + 10.0f) / 0.1f;
        int ix = (int)floorf(tx);
        int iy = (int)floorf(ty);
        ix = min(max(ix, 0), H - 2);   // mathematically already in range; memory safety only
        iy = min(max(iy, 0), W - 2);

        float cx = ((float)ix + 0.5f) * 0.1f - 10.0f;
        float cy = ((float)iy + 0.5f) * 0.1f - 10.0f;
        float dx = (px - cx) / 0.1f;
        float dy = (py - cy) / 0.1f;

        const __half* r0 = env_s + ix * W + iy;
        float v00 = __half2float(r0[0]);
        float v01 = __half2float(r0[1]);
        float v10 = __half2float(r0[W]);
        float v11 = __half2float(r0[W + 1]);

        float vx0 = (1.0f - dx) * v00 + dx * v10;
        float vx1 = (1.0f - dx) * v01 + dx * v11;
        float v   = (1.0f - dy) * vx0 + dy * vx1;

        float d    = oor ? -1.0f : v;
        float viod = fmaxf(10.0f * (0.3f - d), 0.0f);
        acc = fmaf(viod, viod, acc);
    }

    // ---- 4) Block reduction (fp32) ----
    #pragma unroll
    for (int o = 16; o > 0; o >>= 1)
        acc += __shfl_xor_sync(0xffffffffu, acc, o);
    if (lane == 0) redf[warp] = acc;
    __syncthreads();

    if (warp == 0) {
        float s = (lane < THREADS / 32) ? redf[lane] : 0.0f;
        #pragma unroll
        for (int o = 16; o > 0; o >>= 1)
            s += __shfl_xor_sync(0xffffffffu, s, o);
        if (lane == 0) g_partials[b] = s;
    }
    __syncthreads();   // redf reads done before last_flag/redd reuse

    // ---- 5) Last-block-finishes finalization (fence + atomicInc wrap, deterministic) ----
    if (tid == 0) {
        __threadfence();                                   // publish g_partials[b]
        unsigned int old = atomicInc(&g_count, B - 1);     // wraps to 0 on the B-th arrival
        *last_flag = (old == (unsigned int)(B - 1)) ? 1 : 0;
    }
    __syncthreads();

    if (*last_flag) {
        __threadfence();                   // acquire side: see all blocks' partials
        double v = (double)__ldcg(&g_partials[tid]);       // 512 threads, one partial each

        #pragma unroll
        for (int o = 16; o > 0; o >>= 1)
            v += __shfl_xor_sync(0xffffffffu, v, o);
        if (lane == 0) redd[warp] = v;
        __syncthreads();

        if (warp == 0) {
            double s = (lane < THREADS / 32) ? redd[lane] : 0.0;
            #pragma unroll
            for (int o = 8; o > 0; o >>= 1)
                s += __shfl_xor_sync(0xffffffffu, s, o);
            if (lane == 0)
                out[0] = (float)(s / ((double)B * (double)N));
        }
    }
}

extern "C" void kernel_launch(void* const* d_in, const int* in_sizes, int n_in,
                              void* d_out, int out_size)
{
    const float* opState = (const float*)d_in[0];   // (B, N, 2) float32
    const float* envs    = (const float*)d_in[1];   // (B, 1, H, W) float32
    float*       out     = (float*)d_out;           // scalar float32

    // 80000 B slab + 128 B reduce scratch + 16 B flag
    constexpr int SMEM_BYTES = ENV * sizeof(__half) + 16 * sizeof(double) + 16;

    cudaFuncSetAttribute(collision_fused_kernel,
                         cudaFuncAttributeMaxDynamicSharedMemorySize, SMEM_BYTES);

    collision_fused_kernel<<<B, THREADS, SMEM_BYTES>>>(opState, envs, out);
}